// round 12
// baseline (speedup 1.0000x reference)
#include <cuda_runtime.h>
#include <cuda_fp16.h>
#include <cstdint>

// ============================================================================
// BlockConvolutionLean, fp16 mma.sync, PERSISTENT kernel + quad-transpose STG:
//   out = segmented-exclusive-cumsum_8( A @ W^T ) + b_eff, b_eff[0]=2*bias[0]
// - Grid = 304 CTAs (2/SM). CTA fixes an N-half, converts W once, loops M.
// - A: LDG.128 -> cvt f16x2 -> swizzled STS -> ldmatrix; 2-stage, 1 sync/chunk.
// - Epilogue: 8-row segmented exclusive scan (3 shfl) + 4x4 quad transpose
//   (3 shfl rounds) -> each lane stores 8 contiguous floats (2x STG.128).
// ============================================================================

#define MROWS 65536
#define KD 256
#define ND 256
#define BM 128
#define BN 128
#define THREADS 256
#define NCH 4
#define TILES_M (MROWS / BM)           // 512
#define NSM 152
#define GRID (2 * NSM)                 // 304

#define W_REGION 16384
#define OFF_A (4 * W_REGION)
#define A_STAGE 16384
#define SMEM_TOTAL (OFF_A + 2 * A_STAGE)   // 98304 B -> 2 CTAs = 192KB

// ---------------------------------------------------------------------------
__device__ __forceinline__ uint32_t smem_u32(const void* p) {
    uint32_t a;
    asm("{ .reg .u64 t; cvta.to.shared.u64 t, %1; cvt.u32.u64 %0, t; }"
        : "=r"(a) : "l"(p));
    return a;
}
__device__ __forceinline__ void ldsm_x4(uint32_t* r, uint32_t addr) {
    asm volatile("ldmatrix.sync.aligned.m8n8.x4.shared.b16 {%0,%1,%2,%3}, [%4];"
                 : "=r"(r[0]), "=r"(r[1]), "=r"(r[2]), "=r"(r[3]) : "r"(addr));
}
__device__ __forceinline__ void mma_f16(float* c, const uint32_t* a, const uint32_t* b) {
    asm volatile("mma.sync.aligned.m16n8k16.row.col.f32.f16.f16.f32 "
                 "{%0,%1,%2,%3}, {%4,%5,%6,%7}, {%8,%9}, {%0,%1,%2,%3};"
                 : "+f"(c[0]), "+f"(c[1]), "+f"(c[2]), "+f"(c[3])
                 : "r"(a[0]), "r"(a[1]), "r"(a[2]), "r"(a[3]), "r"(b[0]), "r"(b[1]));
}
__device__ __forceinline__ uint32_t h2u(__half2 h) {
    return *reinterpret_cast<uint32_t*>(&h);
}
__device__ __forceinline__ uint2 cvt2(float4 v) {
    __half2 h0 = __floats2half2_rn(v.x, v.y);
    __half2 h1 = __floats2half2_rn(v.z, v.w);
    return make_uint2(h2u(h0), h2u(h1));
}

// ---------------------------------------------------------------------------
__global__ __launch_bounds__(THREADS, 2)
void bc_mma(const float* __restrict__ A, const float* __restrict__ W,
            const float* __restrict__ bias, float* __restrict__ out)
{
    extern __shared__ __align__(1024) char smem[];
    const int tid = threadIdx.x;
    const int lane = tid & 31, w = tid >> 5;
    const int wm = w >> 2, wn = w & 3;         // 2(m) x 4(n); warp tile 64 x 32
    const int n0 = (blockIdx.x & 1) * BN;
    const int mseq = blockIdx.x >> 1;

    // ---- W prologue (ONCE): fp32 LDG -> cvt -> swizzled STS ----
    {
        const float* wg = W + (size_t)n0 * KD;
#pragma unroll
        for (int i = 0; i < 32; i++) {
            int v = tid + i * THREADS;
            int r = v >> 6;
            int f4 = v & 63;
            float4 wv = *reinterpret_cast<const float4*>(wg + (size_t)r * KD + f4 * 4);
            int c = f4 >> 4;
            uint32_t col = (uint32_t)(f4 & 15) * 8;
            uint32_t off = (uint32_t)c * W_REGION + (uint32_t)r * 128 +
                           (col ^ (uint32_t)((r & 7) << 4));
            *reinterpret_cast<uint2*>(smem + off) = cvt2(wv);
        }
    }

    const int rbase = w * 16 + (lane >> 4);
    const uint32_t stscol = (uint32_t)(lane & 15) * 8;
    const uint32_t sb = smem_u32(smem);
    const uint32_t xorv   = (uint32_t)(lane & 7) << 4;
    const uint32_t a_row  = (uint32_t)(wm * 64 + (lane & 15));
    const uint32_t a_csel = ((uint32_t)(lane >> 4)) << 4;
    const uint32_t b_row  = (uint32_t)(wn * 32 + ((lane >> 4) << 3) + (lane & 7));
    const uint32_t b_csel = ((uint32_t)((lane >> 3) & 1)) << 4;

    const int p = lane >> 2;                   // block position / quad id
    const int jq = lane & 3;                   // lane within quad
    float be = __ldg(bias + p);
    if (p == 0) be += be;                      // b_eff[0] = 2*bias[0]

    const size_t a_toff = (size_t)rbase * KD + (lane & 15) * 4;

    // ---- first tile chunk 0 ----
    int mt = mseq;
    {
        const float* ag = A + (size_t)mt * BM * KD + a_toff;
        uint2 pc[8];
#pragma unroll
        for (int j = 0; j < 8; j++)
            pc[j] = cvt2(*reinterpret_cast<const float4*>(ag + j * 2 * KD));
#pragma unroll
        for (int j = 0; j < 8; j++) {
            int row = rbase + 2 * j;
            uint32_t off = (uint32_t)row * 128 + (stscol ^ (uint32_t)((row & 7) << 4));
            *reinterpret_cast<uint2*>(smem + OFF_A + off) = pc[j];
        }
    }
    __syncthreads();

    float acc[4][4][4] = {};

    // ---- persistent tile loop ----
    for (; mt < TILES_M; mt += NSM) {
        const int m0 = mt * BM;
        const float* ag = A + (size_t)m0 * KD + a_toff;
        const int mt_next = mt + NSM;
        const bool has_next = (mt_next < TILES_M);
        const float* ag_next = A + (size_t)mt_next * BM * KD + a_toff;

#pragma unroll
        for (int c = 0; c < NCH; c++) {
            const uint32_t abase = sb + OFF_A + (uint32_t)(c & 1) * A_STAGE;
            const uint32_t wbase = sb + (uint32_t)c * W_REGION;
            char* nstage = smem + OFF_A + ((c + 1) & 1) * A_STAGE;

            const bool do_pre = (c < NCH - 1) || has_next;
            const float* src = (c < NCH - 1) ? (ag + (c + 1) * 64) : ag_next;

            float4 pf[4];
            if (do_pre) {
#pragma unroll
                for (int j = 0; j < 4; j++)
                    pf[j] = *reinterpret_cast<const float4*>(src + j * 2 * KD);
            }

#pragma unroll
            for (int s = 0; s < 2; s++) {
                const uint32_t ksa = (((uint32_t)s * 32) + a_csel) ^ xorv;
                const uint32_t ksb = (((uint32_t)s * 32) + b_csel) ^ xorv;
                uint32_t a[4][4], b[2][4];
#pragma unroll
                for (int mf = 0; mf < 4; mf++)
                    ldsm_x4(a[mf], abase + (a_row + mf * 16) * 128 + ksa);
#pragma unroll
                for (int nfp = 0; nfp < 2; nfp++)
                    ldsm_x4(b[nfp], wbase + (b_row + nfp * 16) * 128 + ksb);
#pragma unroll
                for (int mf = 0; mf < 4; mf++)
#pragma unroll
                    for (int nfp = 0; nfp < 2; nfp++) {
                        mma_f16(acc[mf][2 * nfp],     a[mf], b[nfp]);
                        mma_f16(acc[mf][2 * nfp + 1], a[mf], b[nfp] + 2);
                    }
            }

            if (do_pre) {
#pragma unroll
                for (int j = 0; j < 4; j++) {
                    int row = rbase + 2 * j;
                    uint32_t off = (uint32_t)row * 128 +
                                   (stscol ^ (uint32_t)((row & 7) << 4));
                    *reinterpret_cast<uint2*>(nstage + off) = cvt2(pf[j]);
                }
#pragma unroll
                for (int j = 0; j < 4; j++)
                    pf[j] = *reinterpret_cast<const float4*>(src + (4 + j) * 2 * KD);
            }

#pragma unroll
            for (int s = 2; s < 4; s++) {
                const uint32_t ksa = (((uint32_t)s * 32) + a_csel) ^ xorv;
                const uint32_t ksb = (((uint32_t)s * 32) + b_csel) ^ xorv;
                uint32_t a[4][4], b[2][4];
#pragma unroll
                for (int mf = 0; mf < 4; mf++)
                    ldsm_x4(a[mf], abase + (a_row + mf * 16) * 128 + ksa);
#pragma unroll
                for (int nfp = 0; nfp < 2; nfp++)
                    ldsm_x4(b[nfp], wbase + (b_row + nfp * 16) * 128 + ksb);
#pragma unroll
                for (int mf = 0; mf < 4; mf++)
#pragma unroll
                    for (int nfp = 0; nfp < 2; nfp++) {
                        mma_f16(acc[mf][2 * nfp],     a[mf], b[nfp]);
                        mma_f16(acc[mf][2 * nfp + 1], a[mf], b[nfp] + 2);
                    }
            }

            if (do_pre) {
#pragma unroll
                for (int j = 0; j < 4; j++) {
                    int row = rbase + 2 * (4 + j);
                    uint32_t off = (uint32_t)row * 128 +
                                   (stscol ^ (uint32_t)((row & 7) << 4));
                    *reinterpret_cast<uint2*>(nstage + off) = cvt2(pf[j]);
                }
            }
            __syncthreads();
        }

        // ---- epilogue: scan + quad transpose + STG.128 ----
#pragma unroll
        for (int mf = 0; mf < 4; mf++) {
            // scan all 4 nf frags for this mf
            float e[4][4];
#pragma unroll
            for (int nf = 0; nf < 4; nf++) {
#pragma unroll
                for (int q = 0; q < 4; q++) {
                    float v = acc[mf][nf][q];
                    float sgm = v, t;
                    t = __shfl_up_sync(0xffffffffu, sgm, 4);  if (p >= 1) sgm += t;
                    t = __shfl_up_sync(0xffffffffu, sgm, 8);  if (p >= 2) sgm += t;
                    t = __shfl_up_sync(0xffffffffu, sgm, 16); if (p >= 4) sgm += t;
                    e[nf][q] = sgm - v + be;
                    acc[mf][nf][q] = 0.f;
                }
            }
            // two row-halves: h=0 -> row base+p, h=1 -> +8
#pragma unroll
            for (int h = 0; h < 2; h++) {
                float2 f[4], r[4];
#pragma unroll
                for (int nf = 0; nf < 4; nf++)
                    f[nf] = make_float2(e[nf][2 * h], e[nf][2 * h + 1]);
                // 4x4 quad transpose: lane jq ends with cols jq*8..jq*8+7
                r[jq] = f[jq];
#pragma unroll
                for (int k = 1; k < 4; k++) {
                    int srcj = (jq - k) & 3;
                    float2 snd = f[(jq + k) & 3];
                    int srcl = (lane & ~3) | srcj;
                    r[srcj].x = __shfl_sync(0xffffffffu, snd.x, srcl);
                    r[srcj].y = __shfl_sync(0xffffffffu, snd.y, srcl);
                }
                const int row = m0 + wm * 64 + mf * 16 + p + 8 * h;
                float* op = out + (size_t)row * ND + n0 + wn * 32 + jq * 8;
                *reinterpret_cast<float4*>(op) =
                    make_float4(r[0].x, r[0].y, r[1].x, r[1].y);
                *reinterpret_cast<float4*>(op + 4) =
                    make_float4(r[2].x, r[2].y, r[3].x, r[3].y);
            }
        }
    }
}

// ---------------------------------------------------------------------------
extern "C" void kernel_launch(void* const* d_in, const int* in_sizes, int n_in,
                              void* d_out, int out_size)
{
    const float* A    = (const float*)d_in[0];
    const float* W    = (const float*)d_in[1];
    const float* bias = (const float*)d_in[2];
    float* out = (float*)d_out;

    cudaFuncSetAttribute(bc_mma, cudaFuncAttributeMaxDynamicSharedMemorySize,
                         SMEM_TOTAL);
    bc_mma<<<GRID, THREADS, SMEM_TOTAL>>>(A, W, bias, out);
    (void)in_sizes; (void)n_in; (void)out_size;
}

// round 13
// speedup vs baseline: 1.7454x; 1.7454x over previous
#include <cuda_runtime.h>
#include <cuda_fp16.h>
#include <cstdint>

// ============================================================================
// BlockConvolutionLean, fp16 mma.sync, PERSISTENT kernel + static-index
// quad-transpose epilogue (STG.128):
//   out = segmented-exclusive-cumsum_8( A @ W^T ) + b_eff, b_eff[0]=2*bias[0]
// - Grid = 304 CTAs (2/SM). CTA fixes an N-half, converts W once, loops M.
// - A: LDG.128 -> cvt f16x2 -> swizzled STS -> ldmatrix; 2-stage, 1 sync/chunk.
// - Epilogue: 8-row segmented exclusive scan (3 shfl) + 4x4 quad transpose via
//   shfl_xor butterfly with COMPILE-TIME indices (no local memory), then
//   2x STG.128 per (mf,h): 64B per touched line per instr (2x fewer store wf).
// ============================================================================

#define MROWS 65536
#define KD 256
#define ND 256
#define BM 128
#define BN 128
#define THREADS 256
#define NCH 4
#define TILES_M (MROWS / BM)           // 512
#define NSM 152
#define GRID (2 * NSM)                 // 304

#define W_REGION 16384
#define OFF_A (4 * W_REGION)
#define A_STAGE 16384
#define SMEM_TOTAL (OFF_A + 2 * A_STAGE)   // 98304 B -> 2 CTAs = 192KB

// ---------------------------------------------------------------------------
__device__ __forceinline__ uint32_t smem_u32(const void* p) {
    uint32_t a;
    asm("{ .reg .u64 t; cvta.to.shared.u64 t, %1; cvt.u32.u64 %0, t; }"
        : "=r"(a) : "l"(p));
    return a;
}
__device__ __forceinline__ void ldsm_x4(uint32_t* r, uint32_t addr) {
    asm volatile("ldmatrix.sync.aligned.m8n8.x4.shared.b16 {%0,%1,%2,%3}, [%4];"
                 : "=r"(r[0]), "=r"(r[1]), "=r"(r[2]), "=r"(r[3]) : "r"(addr));
}
__device__ __forceinline__ void mma_f16(float* c, const uint32_t* a, const uint32_t* b) {
    asm volatile("mma.sync.aligned.m16n8k16.row.col.f32.f16.f16.f32 "
                 "{%0,%1,%2,%3}, {%4,%5,%6,%7}, {%8,%9}, {%0,%1,%2,%3};"
                 : "+f"(c[0]), "+f"(c[1]), "+f"(c[2]), "+f"(c[3])
                 : "r"(a[0]), "r"(a[1]), "r"(a[2]), "r"(a[3]), "r"(b[0]), "r"(b[1]));
}
__device__ __forceinline__ uint32_t h2u(__half2 h) {
    return *reinterpret_cast<uint32_t*>(&h);
}
__device__ __forceinline__ uint2 cvt2(float4 v) {
    __half2 h0 = __floats2half2_rn(v.x, v.y);
    __half2 h1 = __floats2half2_rn(v.z, v.w);
    return make_uint2(h2u(h0), h2u(h1));
}
__device__ __forceinline__ void swapf2(float2& a, float2& b) {
    float2 t = a; a = b; b = t;
}
__device__ __forceinline__ float2 shflx2(float2 v, int m) {
    v.x = __shfl_xor_sync(0xffffffffu, v.x, m);
    v.y = __shfl_xor_sync(0xffffffffu, v.y, m);
    return v;
}

// ---------------------------------------------------------------------------
__global__ __launch_bounds__(THREADS, 2)
void bc_mma(const float* __restrict__ A, const float* __restrict__ W,
            const float* __restrict__ bias, float* __restrict__ out)
{
    extern __shared__ __align__(1024) char smem[];
    const int tid = threadIdx.x;
    const int lane = tid & 31, w = tid >> 5;
    const int wm = w >> 2, wn = w & 3;         // 2(m) x 4(n); warp tile 64 x 32
    const int n0 = (blockIdx.x & 1) * BN;
    const int mseq = blockIdx.x >> 1;

    // ---- W prologue (ONCE): fp32 LDG -> cvt -> swizzled STS ----
    {
        const float* wg = W + (size_t)n0 * KD;
#pragma unroll
        for (int i = 0; i < 32; i++) {
            int v = tid + i * THREADS;
            int r = v >> 6;
            int f4 = v & 63;
            float4 wv = *reinterpret_cast<const float4*>(wg + (size_t)r * KD + f4 * 4);
            int c = f4 >> 4;
            uint32_t col = (uint32_t)(f4 & 15) * 8;
            uint32_t off = (uint32_t)c * W_REGION + (uint32_t)r * 128 +
                           (col ^ (uint32_t)((r & 7) << 4));
            *reinterpret_cast<uint2*>(smem + off) = cvt2(wv);
        }
    }

    const int rbase = w * 16 + (lane >> 4);
    const uint32_t stscol = (uint32_t)(lane & 15) * 8;
    const uint32_t sb = smem_u32(smem);
    const uint32_t xorv   = (uint32_t)(lane & 7) << 4;
    const uint32_t a_row  = (uint32_t)(wm * 64 + (lane & 15));
    const uint32_t a_csel = ((uint32_t)(lane >> 4)) << 4;
    const uint32_t b_row  = (uint32_t)(wn * 32 + ((lane >> 4) << 3) + (lane & 7));
    const uint32_t b_csel = ((uint32_t)((lane >> 3) & 1)) << 4;

    const int p = lane >> 2;                   // block position / quad row
    const int jq = lane & 3;                   // lane within quad
    const bool s1 = (jq & 1) != 0;
    const bool s2 = (jq & 2) != 0;
    float be = __ldg(bias + p);
    if (p == 0) be += be;                      // b_eff[0] = 2*bias[0]

    const size_t a_toff = (size_t)rbase * KD + (lane & 15) * 4;

    // ---- first tile chunk 0 ----
    int mt = mseq;
    {
        const float* ag = A + (size_t)mt * BM * KD + a_toff;
        uint2 pc[8];
#pragma unroll
        for (int j = 0; j < 8; j++)
            pc[j] = cvt2(*reinterpret_cast<const float4*>(ag + j * 2 * KD));
#pragma unroll
        for (int j = 0; j < 8; j++) {
            int row = rbase + 2 * j;
            uint32_t off = (uint32_t)row * 128 + (stscol ^ (uint32_t)((row & 7) << 4));
            *reinterpret_cast<uint2*>(smem + OFF_A + off) = pc[j];
        }
    }
    __syncthreads();

    float acc[4][4][4] = {};

    // ---- persistent tile loop ----
    for (; mt < TILES_M; mt += NSM) {
        const int m0 = mt * BM;
        const float* ag = A + (size_t)m0 * KD + a_toff;
        const int mt_next = mt + NSM;
        const bool has_next = (mt_next < TILES_M);
        const float* ag_next = A + (size_t)mt_next * BM * KD + a_toff;

#pragma unroll
        for (int c = 0; c < NCH; c++) {
            const uint32_t abase = sb + OFF_A + (uint32_t)(c & 1) * A_STAGE;
            const uint32_t wbase = sb + (uint32_t)c * W_REGION;
            char* nstage = smem + OFF_A + ((c + 1) & 1) * A_STAGE;

            const bool do_pre = (c < NCH - 1) || has_next;
            const float* src = (c < NCH - 1) ? (ag + (c + 1) * 64) : ag_next;

            float4 pf[4];
            if (do_pre) {
#pragma unroll
                for (int j = 0; j < 4; j++)
                    pf[j] = *reinterpret_cast<const float4*>(src + j * 2 * KD);
            }

#pragma unroll
            for (int s = 0; s < 2; s++) {
                const uint32_t ksa = (((uint32_t)s * 32) + a_csel) ^ xorv;
                const uint32_t ksb = (((uint32_t)s * 32) + b_csel) ^ xorv;
                uint32_t a[4][4], b[2][4];
#pragma unroll
                for (int mf = 0; mf < 4; mf++)
                    ldsm_x4(a[mf], abase + (a_row + mf * 16) * 128 + ksa);
#pragma unroll
                for (int nfp = 0; nfp < 2; nfp++)
                    ldsm_x4(b[nfp], wbase + (b_row + nfp * 16) * 128 + ksb);
#pragma unroll
                for (int mf = 0; mf < 4; mf++)
#pragma unroll
                    for (int nfp = 0; nfp < 2; nfp++) {
                        mma_f16(acc[mf][2 * nfp],     a[mf], b[nfp]);
                        mma_f16(acc[mf][2 * nfp + 1], a[mf], b[nfp] + 2);
                    }
            }

            if (do_pre) {
#pragma unroll
                for (int j = 0; j < 4; j++) {
                    int row = rbase + 2 * j;
                    uint32_t off = (uint32_t)row * 128 +
                                   (stscol ^ (uint32_t)((row & 7) << 4));
                    *reinterpret_cast<uint2*>(nstage + off) = cvt2(pf[j]);
                }
#pragma unroll
                for (int j = 0; j < 4; j++)
                    pf[j] = *reinterpret_cast<const float4*>(src + (4 + j) * 2 * KD);
            }

#pragma unroll
            for (int s = 2; s < 4; s++) {
                const uint32_t ksa = (((uint32_t)s * 32) + a_csel) ^ xorv;
                const uint32_t ksb = (((uint32_t)s * 32) + b_csel) ^ xorv;
                uint32_t a[4][4], b[2][4];
#pragma unroll
                for (int mf = 0; mf < 4; mf++)
                    ldsm_x4(a[mf], abase + (a_row + mf * 16) * 128 + ksa);
#pragma unroll
                for (int nfp = 0; nfp < 2; nfp++)
                    ldsm_x4(b[nfp], wbase + (b_row + nfp * 16) * 128 + ksb);
#pragma unroll
                for (int mf = 0; mf < 4; mf++)
#pragma unroll
                    for (int nfp = 0; nfp < 2; nfp++) {
                        mma_f16(acc[mf][2 * nfp],     a[mf], b[nfp]);
                        mma_f16(acc[mf][2 * nfp + 1], a[mf], b[nfp] + 2);
                    }
            }

            if (do_pre) {
#pragma unroll
                for (int j = 0; j < 4; j++) {
                    int row = rbase + 2 * (4 + j);
                    uint32_t off = (uint32_t)row * 128 +
                                   (stscol ^ (uint32_t)((row & 7) << 4));
                    *reinterpret_cast<uint2*>(nstage + off) = cvt2(pf[j]);
                }
            }
            __syncthreads();
        }

        // ---- epilogue: scan + static quad transpose + STG.128 ----
#pragma unroll
        for (int mf = 0; mf < 4; mf++) {
            float e[4][4];
#pragma unroll
            for (int nf = 0; nf < 4; nf++) {
#pragma unroll
                for (int q = 0; q < 4; q++) {
                    float v = acc[mf][nf][q];
                    float sgm = v, t;
                    t = __shfl_up_sync(0xffffffffu, sgm, 4);  if (p >= 1) sgm += t;
                    t = __shfl_up_sync(0xffffffffu, sgm, 8);  if (p >= 2) sgm += t;
                    t = __shfl_up_sync(0xffffffffu, sgm, 16); if (p >= 4) sgm += t;
                    e[nf][q] = sgm - v + be;
                    acc[mf][nf][q] = 0.f;
                }
            }
#pragma unroll
            for (int h = 0; h < 2; h++) {
                // f[k] = (cols nf=k*8 + jq*2) of row p; transpose within quad
                float2 f0 = make_float2(e[0][2 * h], e[0][2 * h + 1]);
                float2 f1 = make_float2(e[1][2 * h], e[1][2 * h + 1]);
                float2 f2 = make_float2(e[2][2 * h], e[2][2 * h + 1]);
                float2 f3 = make_float2(e[3][2 * h], e[3][2 * h + 1]);

                // stage 1: xor 1 (predicated swaps -> SEL, indices static)
                if (s1) { swapf2(f0, f1); swapf2(f2, f3); }
                f1 = shflx2(f1, 1);
                f3 = shflx2(f3, 1);
                if (s1) { swapf2(f0, f1); swapf2(f2, f3); }
                // stage 2: xor 2
                if (s2) { swapf2(f0, f2); swapf2(f1, f3); }
                f2 = shflx2(f2, 2);
                f3 = shflx2(f3, 2);
                if (s2) { swapf2(f0, f2); swapf2(f1, f3); }

                // lane (p,jq) now holds row p(+8h), cols jq*8 .. jq*8+7
                const int row = m0 + wm * 64 + mf * 16 + p + 8 * h;
                float* op = out + (size_t)row * ND + n0 + wn * 32 + jq * 8;
                *reinterpret_cast<float4*>(op) =
                    make_float4(f0.x, f0.y, f1.x, f1.y);
                *reinterpret_cast<float4*>(op + 4) =
                    make_float4(f2.x, f2.y, f3.x, f3.y);
            }
        }
    }
}

// ---------------------------------------------------------------------------
extern "C" void kernel_launch(void* const* d_in, const int* in_sizes, int n_in,
                              void* d_out, int out_size)
{
    const float* A    = (const float*)d_in[0];
    const float* W    = (const float*)d_in[1];
    const float* bias = (const float*)d_in[2];
    float* out = (float*)d_out;

    cudaFuncSetAttribute(bc_mma, cudaFuncAttributeMaxDynamicSharedMemorySize,
                         SMEM_TOTAL);
    bc_mma<<<GRID, THREADS, SMEM_TOTAL>>>(A, W, bias, out);
    (void)in_sizes; (void)n_in; (void)out_size;
}

// round 14
// speedup vs baseline: 2.0780x; 1.1906x over previous
#include <cuda_runtime.h>
#include <cuda_fp16.h>
#include <cstdint>

// ============================================================================
// BlockConvolutionLean, fp16 mma.sync, PERSISTENT kernel, warpgroup-split
// barriers:
//   out = segmented-exclusive-cumsum_8( A @ W^T ) + b_eff, b_eff[0]=2*bias[0]
// - Grid = 304 CTAs (2/SM). CTA fixes an N-half, converts W once, loops M.
// - A staging is group-local (warps 0-3 <-> rows 0-63, warps 4-7 <-> 64-127),
//   so the per-chunk sync is a NAMED barrier over 128 threads: 4 independent
//   pipelines per SM (2 CTAs x 2 groups) instead of 2.
// - Epilogue: in-register 8-row segmented exclusive scan + streaming STG.
// ============================================================================

#define MROWS 65536
#define KD 256
#define ND 256
#define BM 128
#define BN 128
#define THREADS 256
#define NCH 4
#define TILES_M (MROWS / BM)           // 512
#define NSM 152
#define GRID (2 * NSM)                 // 304

#define W_REGION 16384
#define OFF_A (4 * W_REGION)
#define A_STAGE 16384
#define SMEM_TOTAL (OFF_A + 2 * A_STAGE)   // 98304 B -> 2 CTAs = 192KB

// ---------------------------------------------------------------------------
__device__ __forceinline__ uint32_t smem_u32(const void* p) {
    uint32_t a;
    asm("{ .reg .u64 t; cvta.to.shared.u64 t, %1; cvt.u32.u64 %0, t; }"
        : "=r"(a) : "l"(p));
    return a;
}
__device__ __forceinline__ void ldsm_x4(uint32_t* r, uint32_t addr) {
    asm volatile("ldmatrix.sync.aligned.m8n8.x4.shared.b16 {%0,%1,%2,%3}, [%4];"
                 : "=r"(r[0]), "=r"(r[1]), "=r"(r[2]), "=r"(r[3]) : "r"(addr));
}
__device__ __forceinline__ void mma_f16(float* c, const uint32_t* a, const uint32_t* b) {
    asm volatile("mma.sync.aligned.m16n8k16.row.col.f32.f16.f16.f32 "
                 "{%0,%1,%2,%3}, {%4,%5,%6,%7}, {%8,%9}, {%0,%1,%2,%3};"
                 : "+f"(c[0]), "+f"(c[1]), "+f"(c[2]), "+f"(c[3])
                 : "r"(a[0]), "r"(a[1]), "r"(a[2]), "r"(a[3]), "r"(b[0]), "r"(b[1]));
}
__device__ __forceinline__ uint32_t h2u(__half2 h) {
    return *reinterpret_cast<uint32_t*>(&h);
}
__device__ __forceinline__ uint2 cvt2(float4 v) {
    __half2 h0 = __floats2half2_rn(v.x, v.y);
    __half2 h1 = __floats2half2_rn(v.z, v.w);
    return make_uint2(h2u(h0), h2u(h1));
}
// named barrier over 128 threads (group g uses id g+1; id 0 = __syncthreads)
__device__ __forceinline__ void bar_group(int id) {
    asm volatile("bar.sync %0, 128;" :: "r"(id) : "memory");
}

// ---------------------------------------------------------------------------
__global__ __launch_bounds__(THREADS, 2)
void bc_mma(const float* __restrict__ A, const float* __restrict__ W,
            const float* __restrict__ bias, float* __restrict__ out)
{
    extern __shared__ __align__(1024) char smem[];
    const int tid = threadIdx.x;
    const int lane = tid & 31, w = tid >> 5;
    const int wm = w >> 2, wn = w & 3;         // group = wm; warp tile 64 x 32
    const int barid = wm + 1;                  // named barrier per group
    const int n0 = (blockIdx.x & 1) * BN;
    const int mseq = blockIdx.x >> 1;

    // ---- W prologue (ONCE): fp32 LDG -> cvt -> swizzled STS ----
    {
        const float* wg = W + (size_t)n0 * KD;
#pragma unroll
        for (int i = 0; i < 32; i++) {
            int v = tid + i * THREADS;
            int r = v >> 6;
            int f4 = v & 63;
            float4 wv = *reinterpret_cast<const float4*>(wg + (size_t)r * KD + f4 * 4);
            int c = f4 >> 4;
            uint32_t col = (uint32_t)(f4 & 15) * 8;
            uint32_t off = (uint32_t)c * W_REGION + (uint32_t)r * 128 +
                           (col ^ (uint32_t)((r & 7) << 4));
            *reinterpret_cast<uint2*>(smem + off) = cvt2(wv);
        }
    }

    const int rbase = w * 16 + (lane >> 4);    // group-local: rows wm*64..+63
    const uint32_t stscol = (uint32_t)(lane & 15) * 8;
    const uint32_t sb = smem_u32(smem);
    const uint32_t xorv   = (uint32_t)(lane & 7) << 4;
    const uint32_t a_row  = (uint32_t)(wm * 64 + (lane & 15));
    const uint32_t a_csel = ((uint32_t)(lane >> 4)) << 4;
    const uint32_t b_row  = (uint32_t)(wn * 32 + ((lane >> 4) << 3) + (lane & 7));
    const uint32_t b_csel = ((uint32_t)((lane >> 3) & 1)) << 4;

    const int p = lane >> 2;                   // block position 0..7
    float be = __ldg(bias + p);
    if (p == 0) be += be;                      // b_eff[0] = 2*bias[0]

    const size_t a_toff = (size_t)rbase * KD + (lane & 15) * 4;

    // ---- first tile chunk 0 ----
    int mt = mseq;
    {
        const float* ag = A + (size_t)mt * BM * KD + a_toff;
        uint2 pc[8];
#pragma unroll
        for (int j = 0; j < 8; j++)
            pc[j] = cvt2(*reinterpret_cast<const float4*>(ag + j * 2 * KD));
#pragma unroll
        for (int j = 0; j < 8; j++) {
            int row = rbase + 2 * j;
            uint32_t off = (uint32_t)row * 128 + (stscol ^ (uint32_t)((row & 7) << 4));
            *reinterpret_cast<uint2*>(smem + OFF_A + off) = pc[j];
        }
    }
    __syncthreads();   // W visibility to everyone (once)

    float acc[4][4][4] = {};

    // ---- persistent tile loop (groups drift independently after this) ----
    for (; mt < TILES_M; mt += NSM) {
        const int m0 = mt * BM;
        const float* ag = A + (size_t)m0 * KD + a_toff;
        const int mt_next = mt + NSM;
        const bool has_next = (mt_next < TILES_M);
        const float* ag_next = A + (size_t)mt_next * BM * KD + a_toff;

#pragma unroll
        for (int c = 0; c < NCH; c++) {
            const uint32_t abase = sb + OFF_A + (uint32_t)(c & 1) * A_STAGE;
            const uint32_t wbase = sb + (uint32_t)c * W_REGION;
            char* nstage = smem + OFF_A + ((c + 1) & 1) * A_STAGE;

            const bool do_pre = (c < NCH - 1) || has_next;
            const float* src = (c < NCH - 1) ? (ag + (c + 1) * 64) : ag_next;

            float4 pf[4];
            if (do_pre) {
#pragma unroll
                for (int j = 0; j < 4; j++)
                    pf[j] = *reinterpret_cast<const float4*>(src + j * 2 * KD);
            }

#pragma unroll
            for (int s = 0; s < 2; s++) {
                const uint32_t ksa = (((uint32_t)s * 32) + a_csel) ^ xorv;
                const uint32_t ksb = (((uint32_t)s * 32) + b_csel) ^ xorv;
                uint32_t a[4][4], b[2][4];
#pragma unroll
                for (int mf = 0; mf < 4; mf++)
                    ldsm_x4(a[mf], abase + (a_row + mf * 16) * 128 + ksa);
#pragma unroll
                for (int nfp = 0; nfp < 2; nfp++)
                    ldsm_x4(b[nfp], wbase + (b_row + nfp * 16) * 128 + ksb);
#pragma unroll
                for (int mf = 0; mf < 4; mf++)
#pragma unroll
                    for (int nfp = 0; nfp < 2; nfp++) {
                        mma_f16(acc[mf][2 * nfp],     a[mf], b[nfp]);
                        mma_f16(acc[mf][2 * nfp + 1], a[mf], b[nfp] + 2);
                    }
            }

            if (do_pre) {
#pragma unroll
                for (int j = 0; j < 4; j++) {
                    int row = rbase + 2 * j;
                    uint32_t off = (uint32_t)row * 128 +
                                   (stscol ^ (uint32_t)((row & 7) << 4));
                    *reinterpret_cast<uint2*>(nstage + off) = cvt2(pf[j]);
                }
#pragma unroll
                for (int j = 0; j < 4; j++)
                    pf[j] = *reinterpret_cast<const float4*>(src + (4 + j) * 2 * KD);
            }

#pragma unroll
            for (int s = 2; s < 4; s++) {
                const uint32_t ksa = (((uint32_t)s * 32) + a_csel) ^ xorv;
                const uint32_t ksb = (((uint32_t)s * 32) + b_csel) ^ xorv;
                uint32_t a[4][4], b[2][4];
#pragma unroll
                for (int mf = 0; mf < 4; mf++)
                    ldsm_x4(a[mf], abase + (a_row + mf * 16) * 128 + ksa);
#pragma unroll
                for (int nfp = 0; nfp < 2; nfp++)
                    ldsm_x4(b[nfp], wbase + (b_row + nfp * 16) * 128 + ksb);
#pragma unroll
                for (int mf = 0; mf < 4; mf++)
#pragma unroll
                    for (int nfp = 0; nfp < 2; nfp++) {
                        mma_f16(acc[mf][2 * nfp],     a[mf], b[nfp]);
                        mma_f16(acc[mf][2 * nfp + 1], a[mf], b[nfp] + 2);
                    }
            }

            if (do_pre) {
#pragma unroll
                for (int j = 0; j < 4; j++) {
                    int row = rbase + 2 * (4 + j);
                    uint32_t off = (uint32_t)row * 128 +
                                   (stscol ^ (uint32_t)((row & 7) << 4));
                    *reinterpret_cast<uint2*>(nstage + off) = cvt2(pf[j]);
                }
            }
            bar_group(barid);     // group-local: A stage handoff (4 warps)
        }

        // ---- epilogue: segmented exclusive scan + bias + streaming STG ----
#pragma unroll
        for (int mf = 0; mf < 4; mf++) {
#pragma unroll
            for (int nf = 0; nf < 4; nf++) {
                float e[4];
#pragma unroll
                for (int q = 0; q < 4; q++) {
                    float v = acc[mf][nf][q];
                    float sgm = v, t;
                    t = __shfl_up_sync(0xffffffffu, sgm, 4);  if (p >= 1) sgm += t;
                    t = __shfl_up_sync(0xffffffffu, sgm, 8);  if (p >= 2) sgm += t;
                    t = __shfl_up_sync(0xffffffffu, sgm, 16); if (p >= 4) sgm += t;
                    e[q] = sgm - v + be;
                    acc[mf][nf][q] = 0.f;
                }
                const int row0 = m0 + wm * 64 + mf * 16 + p;
                const int col  = n0 + wn * 32 + nf * 8 + (lane & 3) * 2;
                __stcs(reinterpret_cast<float2*>(out + (size_t)row0 * ND + col),
                       make_float2(e[0], e[1]));
                __stcs(reinterpret_cast<float2*>(out + (size_t)(row0 + 8) * ND + col),
                       make_float2(e[2], e[3]));
            }
        }
    }
}

// ---------------------------------------------------------------------------
extern "C" void kernel_launch(void* const* d_in, const int* in_sizes, int n_in,
                              void* d_out, int out_size)
{
    const float* A    = (const float*)d_in[0];
    const float* W    = (const float*)d_in[1];
    const float* bias = (const float*)d_in[2];
    float* out = (float*)d_out;

    cudaFuncSetAttribute(bc_mma, cudaFuncAttributeMaxDynamicSharedMemorySize,
                         SMEM_TOTAL);
    bc_mma<<<GRID, THREADS, SMEM_TOTAL>>>(A, W, bias, out);
    (void)in_sizes; (void)n_in; (void)out_size;
}

// round 15
// speedup vs baseline: 2.0981x; 1.0097x over previous
#include <cuda_runtime.h>
#include <cuda_fp16.h>
#include <cstdint>

// ============================================================================
// BlockConvolutionLean, fp16 mma.sync, PERSISTENT kernel, warpgroup barriers,
// SCAN FUSED INTO THE A OPERAND:
//   out[8b+i] = (sum_{j<i} A[8b+j]) @ W^T + b_eff   (exclusive prefix = linear
//   op on A rows) -> GEMM on prefix-summed A-tilde; NO epilogue scan at all.
// - Grid = 304 CTAs (2/SM). CTA fixes an N-half, converts W once, loops M.
// - A: coalesced LDG.128 -> in-register 8-row exclusive prefix -> cvt f16x2 ->
//   swizzled STS -> ldmatrix; 2-stage, 1 group-barrier per chunk.
// - Epilogue: acc + bias, streaming STG (no shfl).
// ============================================================================

#define MROWS 65536
#define KD 256
#define ND 256
#define BM 128
#define BN 128
#define THREADS 256
#define NCH 4
#define TILES_M (MROWS / BM)           // 512
#define NSM 152
#define GRID (2 * NSM)                 // 304

#define W_REGION 16384
#define OFF_A (4 * W_REGION)
#define A_STAGE 16384
#define SMEM_TOTAL (OFF_A + 2 * A_STAGE)   // 98304 B -> 2 CTAs = 192KB

// ---------------------------------------------------------------------------
__device__ __forceinline__ uint32_t smem_u32(const void* p) {
    uint32_t a;
    asm("{ .reg .u64 t; cvta.to.shared.u64 t, %1; cvt.u32.u64 %0, t; }"
        : "=r"(a) : "l"(p));
    return a;
}
__device__ __forceinline__ void ldsm_x4(uint32_t* r, uint32_t addr) {
    asm volatile("ldmatrix.sync.aligned.m8n8.x4.shared.b16 {%0,%1,%2,%3}, [%4];"
                 : "=r"(r[0]), "=r"(r[1]), "=r"(r[2]), "=r"(r[3]) : "r"(addr));
}
__device__ __forceinline__ void mma_f16(float* c, const uint32_t* a, const uint32_t* b) {
    asm volatile("mma.sync.aligned.m16n8k16.row.col.f32.f16.f16.f32 "
                 "{%0,%1,%2,%3}, {%4,%5,%6,%7}, {%8,%9}, {%0,%1,%2,%3};"
                 : "+f"(c[0]), "+f"(c[1]), "+f"(c[2]), "+f"(c[3])
                 : "r"(a[0]), "r"(a[1]), "r"(a[2]), "r"(a[3]), "r"(b[0]), "r"(b[1]));
}
__device__ __forceinline__ uint32_t h2u(__half2 h) {
    return *reinterpret_cast<uint32_t*>(&h);
}
__device__ __forceinline__ uint2 cvt2(float4 v) {
    __half2 h0 = __floats2half2_rn(v.x, v.y);
    __half2 h1 = __floats2half2_rn(v.z, v.w);
    return make_uint2(h2u(h0), h2u(h1));
}
__device__ __forceinline__ void add4(float4& a, const float4& b) {
    a.x += b.x; a.y += b.y; a.z += b.z; a.w += b.w;
}
// named barrier over 128 threads (group g uses id g+1)
__device__ __forceinline__ void bar_group(int id) {
    asm volatile("bar.sync %0, 128;" :: "r"(id) : "memory");
}

// ---------------------------------------------------------------------------
__global__ __launch_bounds__(THREADS, 2)
void bc_mma(const float* __restrict__ A, const float* __restrict__ W,
            const float* __restrict__ bias, float* __restrict__ out)
{
    extern __shared__ __align__(1024) char smem[];
    const int tid = threadIdx.x;
    const int lane = tid & 31, w = tid >> 5;
    const int wm = w >> 2, wn = w & 3;         // group = wm; warp tile 64 x 32
    const int barid = wm + 1;
    const int n0 = (blockIdx.x & 1) * BN;
    const int mseq = blockIdx.x >> 1;

    // ---- W prologue (ONCE): fp32 LDG -> cvt -> swizzled STS ----
    {
        const float* wg = W + (size_t)n0 * KD;
#pragma unroll
        for (int i = 0; i < 32; i++) {
            int v = tid + i * THREADS;
            int r = v >> 6;
            int f4 = v & 63;
            float4 wv = *reinterpret_cast<const float4*>(wg + (size_t)r * KD + f4 * 4);
            int c = f4 >> 4;
            uint32_t col = (uint32_t)(f4 & 15) * 8;
            uint32_t off = (uint32_t)c * W_REGION + (uint32_t)r * 128 +
                           (col ^ (uint32_t)((r & 7) << 4));
            *reinterpret_cast<uint2*>(smem + off) = cvt2(wv);
        }
    }

    // A loader mapping: thread owns one aligned 8-row block slice.
    // rows rb8..rb8+7, cols (lane&15)*4 within the chunk.
    const int rb8 = w * 16 + (lane >> 4) * 8;        // 8-aligned
    const uint32_t stscol = (uint32_t)(lane & 15) * 8;
    const uint32_t sb = smem_u32(smem);
    const uint32_t xorv   = (uint32_t)(lane & 7) << 4;
    const uint32_t a_row  = (uint32_t)(wm * 64 + (lane & 15));
    const uint32_t a_csel = ((uint32_t)(lane >> 4)) << 4;
    const uint32_t b_row  = (uint32_t)(wn * 32 + ((lane >> 4) << 3) + (lane & 7));
    const uint32_t b_csel = ((uint32_t)((lane >> 3) & 1)) << 4;

    const int p = lane >> 2;                   // block position of output row
    float be = __ldg(bias + p);
    if (p == 0) be += be;                      // b_eff[0] = 2*bias[0]

    const size_t a_toff = (size_t)rb8 * KD + (lane & 15) * 4;

    // ---- first tile chunk 0: LDG 8 rows -> exclusive prefix -> cvt -> STS ----
    int mt = mseq;
    {
        const float* ag = A + (size_t)mt * BM * KD + a_toff;
        float4 pf[8];
#pragma unroll
        for (int j = 0; j < 8; j++)
            pf[j] = *reinterpret_cast<const float4*>(ag + j * KD);
        float4 run = make_float4(0.f, 0.f, 0.f, 0.f);
#pragma unroll
        for (int j = 0; j < 8; j++) {
            uint32_t off = (uint32_t)(rb8 + j) * 128 +
                           (stscol ^ ((uint32_t)j << 4));
            *reinterpret_cast<uint2*>(smem + OFF_A + off) = cvt2(run);
            add4(run, pf[j]);
        }
    }
    __syncthreads();   // W + first stage visibility (once)

    float acc[4][4][4] = {};

    // ---- persistent tile loop (groups drift independently) ----
    for (; mt < TILES_M; mt += NSM) {
        const int m0 = mt * BM;
        const float* ag = A + (size_t)m0 * KD + a_toff;
        const int mt_next = mt + NSM;
        const bool has_next = (mt_next < TILES_M);
        const float* ag_next = A + (size_t)mt_next * BM * KD + a_toff;

#pragma unroll
        for (int c = 0; c < NCH; c++) {
            const uint32_t abase = sb + OFF_A + (uint32_t)(c & 1) * A_STAGE;
            const uint32_t wbase = sb + (uint32_t)c * W_REGION;
            char* nstage = smem + OFF_A + ((c + 1) & 1) * A_STAGE;

            const bool do_pre = (c < NCH - 1) || has_next;
            const float* src = (c < NCH - 1) ? (ag + (c + 1) * 64) : ag_next;

            float4 pf[4];
            float4 run = make_float4(0.f, 0.f, 0.f, 0.f);
            if (do_pre) {
#pragma unroll
                for (int j = 0; j < 4; j++)
                    pf[j] = *reinterpret_cast<const float4*>(src + j * KD);
            }

#pragma unroll
            for (int s = 0; s < 2; s++) {
                const uint32_t ksa = (((uint32_t)s * 32) + a_csel) ^ xorv;
                const uint32_t ksb = (((uint32_t)s * 32) + b_csel) ^ xorv;
                uint32_t a[4][4], b[2][4];
#pragma unroll
                for (int mf = 0; mf < 4; mf++)
                    ldsm_x4(a[mf], abase + (a_row + mf * 16) * 128 + ksa);
#pragma unroll
                for (int nfp = 0; nfp < 2; nfp++)
                    ldsm_x4(b[nfp], wbase + (b_row + nfp * 16) * 128 + ksb);
#pragma unroll
                for (int mf = 0; mf < 4; mf++)
#pragma unroll
                    for (int nfp = 0; nfp < 2; nfp++) {
                        mma_f16(acc[mf][2 * nfp],     a[mf], b[nfp]);
                        mma_f16(acc[mf][2 * nfp + 1], a[mf], b[nfp] + 2);
                    }
            }

            if (do_pre) {
                // rows j=0..3: store exclusive prefix, accumulate
#pragma unroll
                for (int j = 0; j < 4; j++) {
                    uint32_t off = (uint32_t)(rb8 + j) * 128 +
                                   (stscol ^ ((uint32_t)j << 4));
                    *reinterpret_cast<uint2*>(nstage + off) = cvt2(run);
                    add4(run, pf[j]);
                }
#pragma unroll
                for (int j = 0; j < 4; j++)
                    pf[j] = *reinterpret_cast<const float4*>(src + (4 + j) * KD);
            }

#pragma unroll
            for (int s = 2; s < 4; s++) {
                const uint32_t ksa = (((uint32_t)s * 32) + a_csel) ^ xorv;
                const uint32_t ksb = (((uint32_t)s * 32) + b_csel) ^ xorv;
                uint32_t a[4][4], b[2][4];
#pragma unroll
                for (int mf = 0; mf < 4; mf++)
                    ldsm_x4(a[mf], abase + (a_row + mf * 16) * 128 + ksa);
#pragma unroll
                for (int nfp = 0; nfp < 2; nfp++)
                    ldsm_x4(b[nfp], wbase + (b_row + nfp * 16) * 128 + ksb);
#pragma unroll
                for (int mf = 0; mf < 4; mf++)
#pragma unroll
                    for (int nfp = 0; nfp < 2; nfp++) {
                        mma_f16(acc[mf][2 * nfp],     a[mf], b[nfp]);
                        mma_f16(acc[mf][2 * nfp + 1], a[mf], b[nfp] + 2);
                    }
            }

            if (do_pre) {
                // rows j=4..7
#pragma unroll
                for (int j = 0; j < 4; j++) {
                    uint32_t off = (uint32_t)(rb8 + 4 + j) * 128 +
                                   (stscol ^ ((uint32_t)(4 + j) << 4));
                    *reinterpret_cast<uint2*>(nstage + off) = cvt2(run);
                    add4(run, pf[j]);
                }
            }
            bar_group(barid);
        }

        // ---- epilogue: bias + streaming STG (NO scan — it's in A-tilde) ----
#pragma unroll
        for (int mf = 0; mf < 4; mf++) {
#pragma unroll
            for (int nf = 0; nf < 4; nf++) {
                const int row0 = m0 + wm * 64 + mf * 16 + p;
                const int col  = n0 + wn * 32 + nf * 8 + (lane & 3) * 2;
                float e0 = acc[mf][nf][0] + be;
                float e1 = acc[mf][nf][1] + be;
                float e2 = acc[mf][nf][2] + be;
                float e3 = acc[mf][nf][3] + be;
                acc[mf][nf][0] = 0.f; acc[mf][nf][1] = 0.f;
                acc[mf][nf][2] = 0.f; acc[mf][nf][3] = 0.f;
                __stcs(reinterpret_cast<float2*>(out + (size_t)row0 * ND + col),
                       make_float2(e0, e1));
                __stcs(reinterpret_cast<float2*>(out + (size_t)(row0 + 8) * ND + col),
                       make_float2(e2, e3));
            }
        }
    }
}

// ---------------------------------------------------------------------------
extern "C" void kernel_launch(void* const* d_in, const int* in_sizes, int n_in,
                              void* d_out, int out_size)
{
    const float* A    = (const float*)d_in[0];
    const float* W    = (const float*)d_in[1];
    const float* bias = (const float*)d_in[2];
    float* out = (float*)d_out;

    cudaFuncSetAttribute(bc_mma, cudaFuncAttributeMaxDynamicSharedMemorySize,
                         SMEM_TOTAL);
    bc_mma<<<GRID, THREADS, SMEM_TOTAL>>>(A, W, bias, out);
    (void)in_sizes; (void)n_in; (void)out_size;
}